// round 6
// baseline (speedup 1.0000x reference)
#include <cuda_runtime.h>
#include <cuda_bf16.h>
#include <mma.h>
#include <math.h>
#include <stdint.h>

using namespace nvcuda;

#define SEQ   512
#define BATCH 128
#define EDIM  1024
#define HDIM  1024
#define GRID  128            // persistent blocks, 1/SM via smem (<=148 SMs)
#define BP    136            // padded batch stride (128 data + 8 pad), 272 B rows
#define CHUNKB (128 * BP * 2)          // one K-chunk: 128 k-rows x 272 B = 34816 B
#define WS_LD 2056                     // Wcat row stride (2048 K + 8 pad)
#define GS_LD 36
#define PERS_SMEM_BYTES (32 * WS_LD * 2 + 2 * CHUNKB)   // 131584 + 69632 = 201216

// ---- device scratch (no allocations allowed) ----
__device__ __align__(256) __nv_bfloat16 g_xq[(size_t)SEQ * 1024 * BP]; // [s][k][b+pad] bf16
__device__ __align__(256) __nv_bfloat16 g_hb[2][1024 * BP];            // [hc][b+pad] bf16, double buffered
__device__ __align__(256) float g_hf[1024 * BATCH];                    // final h, [hc][b] fp32
__device__ __align__(256) float g_c[1024 * BATCH];                     // cell state [hc][b]
__device__ unsigned g_cnt[8];                                          // per-group monotonic counters

__device__ __forceinline__ unsigned sptr(const void* p) {
    return (unsigned)__cvta_generic_to_shared(p);
}
__device__ __forceinline__ void mbar_init(uint64_t* m, unsigned count) {
    asm volatile("mbarrier.init.shared.b64 [%0], %1;" :: "r"(sptr(m)), "r"(count));
}
__device__ __forceinline__ void mbar_expect(uint64_t* m, unsigned bytes) {
    asm volatile("mbarrier.arrive.expect_tx.shared.b64 _, [%0], %1;"
                 :: "r"(sptr(m)), "r"(bytes) : "memory");
}
__device__ __forceinline__ void bulk_g2s(void* dst, const void* src, unsigned bytes, uint64_t* m) {
    asm volatile("cp.async.bulk.shared::cta.global.mbarrier::complete_tx::bytes [%0], [%1], %2, [%3];"
                 :: "r"(sptr(dst)), "l"(src), "r"(bytes), "r"(sptr(m)) : "memory");
}
__device__ __forceinline__ void mbar_wait(uint64_t* m, unsigned parity) {
    asm volatile(
        "{\n\t.reg .pred P;\n\t"
        "W%=:\n\t"
        "mbarrier.try_wait.parity.shared.b64 P, [%0], %1;\n\t"
        "@P bra D%=;\n\t"
        "bra W%=;\n\t"
        "D%=:\n\t}"
        :: "r"(sptr(m)), "r"(parity) : "memory");
}
__device__ __forceinline__ void wait_cnt(const unsigned* cnt, unsigned target) {
    unsigned v;
    do {
        asm volatile("ld.acquire.gpu.global.u32 %0, [%1];" : "=r"(v) : "l"(cnt));
    } while (v < target);
}

// ---------------------------------------------------------------------------
// Kernel 0: reset state (deterministic across graph replays)
// ---------------------------------------------------------------------------
__global__ void zero_state_kernel() {
    int i = blockIdx.x * blockDim.x + threadIdx.x;      // 131072 threads
    if (i < 1024 * BP / 2) ((unsigned*)g_hb[0])[i] = 0u;
    if (i < 1024 * BATCH)  g_c[i] = 0.f;
    if (i < 8)             g_cnt[i] = 0u;
}

// ---------------------------------------------------------------------------
// Kernel 1: embedding gather -> bf16, transposed+padded: g_xq[s][k][b]
// One block per timestep s. Tile-transpose through smem.
// ---------------------------------------------------------------------------
__global__ __launch_bounds__(256)
void gather_kernel(const int* __restrict__ X, const float* __restrict__ embd) {
    __shared__ int tok[128];
    __shared__ __nv_bfloat16 t_sm[64][BP];
    const int s   = blockIdx.x;
    const int tid = threadIdx.x;

    if (tid < 128) tok[tid] = X[s * 128 + tid];
    __syncthreads();

    for (int kc = 0; kc < 16; kc++) {
        #pragma unroll
        for (int i = 0; i < 8; i++) {
            int slot = i * 256 + tid;            // 2048 = 128 b x 16 float4
            int b = slot >> 4, kv = slot & 15;
            float4 v = *(const float4*)(embd + (size_t)tok[b] * EDIM + kc * 64 + kv * 4);
            t_sm[kv * 4 + 0][b] = __float2bfloat16(v.x);
            t_sm[kv * 4 + 1][b] = __float2bfloat16(v.y);
            t_sm[kv * 4 + 2][b] = __float2bfloat16(v.z);
            t_sm[kv * 4 + 3][b] = __float2bfloat16(v.w);
        }
        __syncthreads();
        #pragma unroll
        for (int i = 0; i < 4; i++) {
            int slot = i * 256 + tid;            // 1024 = 64 rows x 16 uint4
            int row = slot >> 4, seg = slot & 15;
            *(uint4*)(g_xq + ((size_t)s * 1024 + kc * 64 + row) * BP + seg * 8) =
                *(uint4*)&t_sm[row][seg * 8];
        }
        __syncthreads();
    }
}

// ---------------------------------------------------------------------------
// Kernel 2: persistent fused LSTM. gates = [x_t | h] @ [Wih | Whh]^T in one
// K=2048 accumulation. 16 K-chunks of 128, each staged as ONE cp.async.bulk.
// Block owns 8 hidden cols; Wcat slice resident in smem. Fine-grained
// producer counters replace the global barrier (x-chunks need no sync).
// ---------------------------------------------------------------------------
__global__ __launch_bounds__(256, 1)
void lstm_persistent_kernel(const float* __restrict__ Wih,
                            const float* __restrict__ Whh,
                            const float* __restrict__ bih,
                            const float* __restrict__ bhh) {
    extern __shared__ __align__(128) unsigned char smem_raw[];
    __nv_bfloat16* Ws = (__nv_bfloat16*)smem_raw;                    // [32][WS_LD]
    __nv_bfloat16* bufs[2];
    bufs[0] = Ws + 32 * WS_LD;                                       // [128][BP]
    bufs[1] = bufs[0] + 128 * BP;
    float* Gs = (float*)bufs[0];                                     // epilogue overlay
    __shared__ uint64_t mbar[2];
    __shared__ float bsum[32];

    const int c0   = blockIdx.x * 8;
    const int tid  = threadIdx.x;       // 256
    const int warp = tid >> 5;
    const int wm   = warp >> 1;         // 0..3 -> 32 batch rows
    const int wn   = warp & 1;          // 0..1 -> 16 gate cols

    // ---- Wcat = [Wih | Whh] slice -> bf16 smem (once) ----
    for (int i = tid; i < 32 * 512; i += 256) {      // 16384 float4
        int n  = i >> 9;                              // row 0..31
        int kv = i & 511;                             // float4 idx (2048 K)
        int g = n >> 3, col = n & 7;
        size_t rowoff = (size_t)(g * HDIM + c0 + col) * 1024;
        float4 v = (kv < 256) ? *(const float4*)(Wih + rowoff + kv * 4)
                              : *(const float4*)(Whh + rowoff + (kv - 256) * 4);
        __nv_bfloat162 p0 = __floats2bfloat162_rn(v.x, v.y);
        __nv_bfloat162 p1 = __floats2bfloat162_rn(v.z, v.w);
        uint2 u = make_uint2(*(unsigned*)&p0, *(unsigned*)&p1);
        *(uint2*)&Ws[(size_t)n * WS_LD + kv * 4] = u;
    }
    if (tid < 32) {
        int g = tid >> 3, col = tid & 7;
        int r = g * HDIM + c0 + col;
        bsum[tid] = bih[r] + bhh[r];
    }
    if (tid == 0) { mbar_init(&mbar[0], 1); mbar_init(&mbar[1], 1); }
    __syncthreads();

    for (int s = 0; s < SEQ; s++) {
        const __nv_bfloat16* hin = g_hb[s & 1];
        __nv_bfloat16*       hob = g_hb[(s + 1) & 1];
        const __nv_bfloat16* xs  = g_xq + (size_t)s * 1024 * BP;

        // chunk c source: c<8 -> x (no dependency), c>=8 -> h (needs group c-8)
        // prologue: stage chunks 0,1 (both x)
        if (tid == 0) {
            mbar_expect(&mbar[0], CHUNKB);
            bulk_g2s(bufs[0], xs, CHUNKB, &mbar[0]);
            mbar_expect(&mbar[1], CHUNKB);
            bulk_g2s(bufs[1], xs + (size_t)128 * BP, CHUNKB, &mbar[1]);
        }

        wmma::fragment<wmma::accumulator, 16, 16, 16, float> acc[2];
        #pragma unroll
        for (int i = 0; i < 2; i++) wmma::fill_fragment(acc[i], 0.0f);

        for (int c = 0; c < 16; c++) {
            // parity of this chunk's completion on mbar[c&1]
            unsigned par = (unsigned)((s * 8 + (c >> 1)) & 1);
            mbar_wait(&mbar[c & 1], par);

            const __nv_bfloat16* Hc = bufs[c & 1];
            #pragma unroll
            for (int ks = 0; ks < 8; ks++) {
                wmma::fragment<wmma::matrix_b, 16, 16, 16, __nv_bfloat16, wmma::col_major> bf;
                wmma::load_matrix_sync(bf, Ws + (size_t)(wn * 16) * WS_LD + c * 128 + ks * 16, WS_LD);
                #pragma unroll
                for (int i = 0; i < 2; i++) {
                    wmma::fragment<wmma::matrix_a, 16, 16, 16, __nv_bfloat16, wmma::col_major> af;
                    wmma::load_matrix_sync(af, Hc + (size_t)(ks * 16) * BP + wm * 32 + i * 16, BP);
                    wmma::mma_sync(acc[i], af, bf, acc[i]);
                }
            }
            __syncthreads();        // everyone done reading bufs[c&1]

            if (c + 2 < 16 && tid == 0) {
                int nc = c + 2;
                const __nv_bfloat16* src;
                if (nc < 8) {
                    src = xs + (size_t)nc * 128 * BP;
                } else {
                    wait_cnt(&g_cnt[nc - 8], 16u * (unsigned)s);   // producers of step s-1
                    src = hin + (size_t)(nc - 8) * 128 * BP;
                }
                mbar_expect(&mbar[c & 1], CHUNKB);
                bulk_g2s(bufs[c & 1], src, CHUNKB, &mbar[c & 1]);
            }
        }

        // ---- epilogue: gates in acc -> activations -> c/h ----
        #pragma unroll
        for (int i = 0; i < 2; i++)
            wmma::store_matrix_sync(Gs + (size_t)(wm * 32 + i * 16) * GS_LD + wn * 16, acc[i],
                                    GS_LD, wmma::mem_row_major);
        __syncthreads();

        #pragma unroll
        for (int q = 0; q < 4; q++) {
            int cell = q * 256 + tid;         // 0..1023
            int bl = cell & 127;              // batch row
            int c  = cell >> 7;               // owned col 0..7
            int hc = c0 + c;

            float gi = Gs[bl * GS_LD +      c] + bsum[     c];
            float gf = Gs[bl * GS_LD +  8 + c] + bsum[ 8 + c];
            float gg = Gs[bl * GS_LD + 16 + c] + bsum[16 + c];
            float go = Gs[bl * GS_LD + 24 + c] + bsum[24 + c];

            float iv = 1.f / (1.f + expf(-gi));
            float fv = 1.f / (1.f + expf(-gf));
            float ov = 1.f / (1.f + expf(-go));

            int ci = hc * BATCH + bl;
            float cn = fv * g_c[ci] + iv * tanhf(gg);
            float hn = ov * tanhf(cn);
            g_c[ci] = cn;
            hob[(size_t)hc * BP + bl] = __float2bfloat16(hn);
            if (s == SEQ - 1) g_hf[(size_t)hc * BATCH + bl] = hn;
        }
        __syncthreads();          // Gs reads + h stores done before arrival/reuse

        if (tid == 0) {
            __threadfence();
            atomicAdd(&g_cnt[blockIdx.x >> 4], 1u);
        }
    }
}

// ---------------------------------------------------------------------------
// Kernel 3: log_softmax over BATCH axis of final h (g_hf is [hc][b]).
// ---------------------------------------------------------------------------
__global__ void logsoftmax_kernel(float* __restrict__ out) {
    const int hj = blockIdx.x;
    const int t  = threadIdx.x;   // 128

    float v = g_hf[(size_t)hj * BATCH + t];

    __shared__ float rm[4], rs[4];
    float m = v;
    #pragma unroll
    for (int o = 16; o; o >>= 1) m = fmaxf(m, __shfl_xor_sync(0xffffffffu, m, o));
    if ((t & 31) == 0) rm[t >> 5] = m;
    __syncthreads();
    m = fmaxf(fmaxf(rm[0], rm[1]), fmaxf(rm[2], rm[3]));

    float e = expf(v - m);
    float ssum = e;
    #pragma unroll
    for (int o = 16; o; o >>= 1) ssum += __shfl_xor_sync(0xffffffffu, ssum, o);
    if ((t & 31) == 0) rs[t >> 5] = ssum;
    __syncthreads();
    ssum = rs[0] + rs[1] + rs[2] + rs[3];

    out[(size_t)t * HDIM + hj] = (v - m) - logf(ssum);
}

// ---------------------------------------------------------------------------
extern "C" void kernel_launch(void* const* d_in, const int* in_sizes, int n_in,
                              void* d_out, int out_size) {
    (void)in_sizes; (void)n_in; (void)out_size;
    const int*   X    = (const int*)d_in[0];
    const float* embd = (const float*)d_in[1];
    const float* Wih  = (const float*)d_in[2];
    const float* Whh  = (const float*)d_in[3];
    const float* bih  = (const float*)d_in[4];
    const float* bhh  = (const float*)d_in[5];
    float* out = (float*)d_out;

    static int configured = 0;
    if (!configured) {
        cudaFuncSetAttribute(lstm_persistent_kernel,
                             cudaFuncAttributeMaxDynamicSharedMemorySize,
                             PERS_SMEM_BYTES);
        configured = 1;
    }

    zero_state_kernel<<<512, 256>>>();
    gather_kernel<<<SEQ, 256>>>(X, embd);
    lstm_persistent_kernel<<<GRID, 256, PERS_SMEM_BYTES>>>(Wih, Whh, bih, bhh);
    logsoftmax_kernel<<<HDIM, BATCH>>>(out);
}

// round 8
// speedup vs baseline: 1.3771x; 1.3771x over previous
#include <cuda_runtime.h>
#include <cuda_bf16.h>
#include <mma.h>
#include <math.h>
#include <stdint.h>

using namespace nvcuda;

#define SEQ   512
#define BATCH 128
#define EDIM  1024
#define HDIM  1024
#define GRID  128
#define WS_LD 1032                     // 1024 K + 8 pad (elements)
#define HS_LD 1032
#define GS_LD 36                       // MUST be multiple of 4 floats (16B) for wmma
#define PERS_SMEM (3 * 32 * WS_LD * 2) // W + 2 h-chunk buffers = 198144 B
#define EMB_SMEM  (128 * 136 * 4)      // stage tile = 69632 B (overlays A/B bufs)

// ---- device scratch (no allocations allowed) ----
__device__ __align__(256) __nv_bfloat16 g_xq[(size_t)SEQ * 4096 * BATCH]; // [s][n][b] bf16
__device__ __align__(256) __nv_bfloat16 g_hb[2][BATCH * HDIM];            // [b][k] bf16, dbl-buffered
__device__ __align__(256) float g_hf[HDIM * BATCH];                       // final h, [hc][b]
__device__ __align__(256) float g_c[BATCH * HDIM];                        // cell state [b][hc]
__device__ unsigned g_arrive;

__device__ __forceinline__ unsigned sptr(const void* p) {
    return (unsigned)__cvta_generic_to_shared(p);
}
__device__ __forceinline__ void mbar_init(uint64_t* m, unsigned count) {
    asm volatile("mbarrier.init.shared.b64 [%0], %1;" :: "r"(sptr(m)), "r"(count));
}
__device__ __forceinline__ void mbar_expect(uint64_t* m, unsigned bytes) {
    asm volatile("mbarrier.arrive.expect_tx.shared.b64 _, [%0], %1;"
                 :: "r"(sptr(m)), "r"(bytes) : "memory");
}
__device__ __forceinline__ void bulk_g2s(void* dst, const void* src, unsigned bytes, uint64_t* m) {
    asm volatile("cp.async.bulk.shared::cta.global.mbarrier::complete_tx::bytes [%0], [%1], %2, [%3];"
                 :: "r"(sptr(dst)), "l"(src), "r"(bytes), "r"(sptr(m)) : "memory");
}
__device__ __forceinline__ void mbar_wait(uint64_t* m, unsigned parity) {
    asm volatile(
        "{\n\t.reg .pred P;\n\t"
        "W%=:\n\t"
        "mbarrier.try_wait.parity.acquire.cta.shared::cta.b64 P, [%0], %1;\n\t"
        "@P bra D%=;\n\t"
        "bra W%=;\n\t"
        "D%=:\n\t}"
        :: "r"(sptr(m)), "r"(parity) : "memory");
}

// ---------------------------------------------------------------------------
// Kernel 0: reset state (deterministic across graph replays)
// ---------------------------------------------------------------------------
__global__ void zero_state_kernel() {
    int i = blockIdx.x * blockDim.x + threadIdx.x;   // 131072 threads
    if (i < 16384) ((uint4*)g_hb[0])[i] = make_uint4(0u, 0u, 0u, 0u);
    if (i < 32768) ((float4*)g_c)[i]   = make_float4(0.f, 0.f, 0.f, 0.f);
    if (i == 0) g_arrive = 0u;
}

// ---------------------------------------------------------------------------
// Kernel 1: embedding gather + input projection (bf16 wmma, 128x128 tiles),
// output bf16 TRANSPOSED: g_xq[s][n][b]. Grid (32 n-tiles, 512 steps).
// ---------------------------------------------------------------------------
__global__ __launch_bounds__(256)
void embed_proj_kernel(const int* __restrict__ X,
                       const float* __restrict__ embd,
                       const float* __restrict__ Wih) {
    extern __shared__ __align__(16) unsigned char dyn[];
    __nv_bfloat16* As = (__nv_bfloat16*)dyn;        // [2][128][40]
    __nv_bfloat16* Bs = As + 2 * 128 * 40;          // [2][128][40]
    float* stage = (float*)dyn;                     // overlay after GEMM, col-major ld=136
    __shared__ int tok[128];

    const int s   = blockIdx.y;
    const int nt  = blockIdx.x;
    const int tid = threadIdx.x;
    const int warp = tid >> 5;
    const int wm = warp >> 2;         // 0..1 -> 64 m rows
    const int wn = warp & 3;          // 0..3 -> 32 n cols

    if (tid < 128) tok[tid] = X[s * 128 + tid];
    __syncthreads();

    wmma::fragment<wmma::accumulator, 16, 16, 16, float> acc[4][2];
    #pragma unroll
    for (int i = 0; i < 4; i++)
        #pragma unroll
        for (int j = 0; j < 2; j++) wmma::fill_fragment(acc[i][j], 0.0f);

    int rr[4], kk[4];
    #pragma unroll
    for (int q = 0; q < 4; q++) {
        int slot = q * 256 + tid;
        rr[q] = slot >> 3;
        kk[q] = slot & 7;
    }

    float4 ra[4], rb[4];
    auto ldg_chunk = [&](int kc) {
        #pragma unroll
        for (int q = 0; q < 4; q++) {
            ra[q] = *(const float4*)(embd + (size_t)tok[rr[q]] * EDIM + kc * 32 + kk[q] * 4);
            rb[q] = *(const float4*)(Wih + (size_t)(nt * 128 + rr[q]) * EDIM + kc * 32 + kk[q] * 4);
        }
    };
    auto sts_chunk = [&](int buf) {
        #pragma unroll
        for (int q = 0; q < 4; q++) {
            __nv_bfloat162 a0 = __floats2bfloat162_rn(ra[q].x, ra[q].y);
            __nv_bfloat162 a1 = __floats2bfloat162_rn(ra[q].z, ra[q].w);
            *(uint2*)(As + (size_t)(buf * 128 + rr[q]) * 40 + kk[q] * 4) =
                make_uint2(*(unsigned*)&a0, *(unsigned*)&a1);
            __nv_bfloat162 b0 = __floats2bfloat162_rn(rb[q].x, rb[q].y);
            __nv_bfloat162 b1 = __floats2bfloat162_rn(rb[q].z, rb[q].w);
            *(uint2*)(Bs + (size_t)(buf * 128 + rr[q]) * 40 + kk[q] * 4) =
                make_uint2(*(unsigned*)&b0, *(unsigned*)&b1);
        }
    };

    ldg_chunk(0);
    sts_chunk(0);
    __syncthreads();
    int buf = 0;

    for (int kc = 0; kc < 32; kc++) {
        if (kc < 31) ldg_chunk(kc + 1);
        #pragma unroll
        for (int ks = 0; ks < 2; ks++) {
            wmma::fragment<wmma::matrix_a, 16, 16, 16, __nv_bfloat16, wmma::row_major> af[4];
            wmma::fragment<wmma::matrix_b, 16, 16, 16, __nv_bfloat16, wmma::col_major> bf[2];
            #pragma unroll
            for (int i = 0; i < 4; i++)
                wmma::load_matrix_sync(af[i], As + (size_t)(buf * 128 + wm * 64 + i * 16) * 40 + ks * 16, 40);
            #pragma unroll
            for (int j = 0; j < 2; j++)
                wmma::load_matrix_sync(bf[j], Bs + (size_t)(buf * 128 + wn * 32 + j * 16) * 40 + ks * 16, 40);
            #pragma unroll
            for (int i = 0; i < 4; i++)
                #pragma unroll
                for (int j = 0; j < 2; j++)
                    wmma::mma_sync(acc[i][j], af[i], bf[j], acc[i][j]);
        }
        if (kc < 31) {
            sts_chunk(buf ^ 1);
            __syncthreads();
            buf ^= 1;
        }
    }

    __syncthreads();   // GEMM reads of As/Bs done; overlay stage
    // stage (m=b, n) at b + n*136 (col-major, ld=136 -> 544B, 16B-aligned)
    #pragma unroll
    for (int i = 0; i < 4; i++)
        #pragma unroll
        for (int j = 0; j < 2; j++)
            wmma::store_matrix_sync(stage + (wm * 64 + i * 16) + (size_t)(wn * 32 + j * 16) * 136,
                                    acc[i][j], 136, wmma::mem_col_major);
    __syncthreads();

    // convert + write: row n = 128 bf16 contiguous in b
    #pragma unroll
    for (int q = 0; q < 8; q++) {
        int slot = q * 256 + tid;        // 2048 = 128 n x 16 segments
        int n   = slot >> 4;
        int seg = slot & 15;
        const float* src = stage + (size_t)n * 136 + seg * 8;
        __nv_bfloat162 p0 = __floats2bfloat162_rn(src[0], src[1]);
        __nv_bfloat162 p1 = __floats2bfloat162_rn(src[2], src[3]);
        __nv_bfloat162 p2 = __floats2bfloat162_rn(src[4], src[5]);
        __nv_bfloat162 p3 = __floats2bfloat162_rn(src[6], src[7]);
        uint4 u = make_uint4(*(unsigned*)&p0, *(unsigned*)&p1, *(unsigned*)&p2, *(unsigned*)&p3);
        *(uint4*)(g_xq + ((size_t)s * 4096 + nt * 128 + n) * 128 + seg * 8) = u;
    }
}

// ---------------------------------------------------------------------------
// Kernel 2: persistent LSTM. Batch-chunked: per step, 4 chunks of 32 batch
// rows; each chunk staged as 32 x cp.async.bulk (2KB/row) into padded smem,
// then full-K GEMM (8 warps: 2m x 2n x 2k-split) + immediate epilogue.
// W_hh slice (32 gate-cols) resident in smem bf16 for the whole sequence.
// ---------------------------------------------------------------------------
__device__ __forceinline__ void stage_chunk(__nv_bfloat16* buf, const __nv_bfloat16* hin,
                                            int chunk, uint64_t* mb, int lane) {
    if (lane == 0) mbar_expect(mb, 32 * 2048);
    __syncwarp();
    bulk_g2s(buf + (size_t)lane * HS_LD,
             hin + (size_t)(chunk * 32 + lane) * HDIM, 2048, mb);
}

__global__ __launch_bounds__(256, 1)
void lstm_persistent_kernel(const float* __restrict__ Whh,
                            const float* __restrict__ bih,
                            const float* __restrict__ bhh) {
    extern __shared__ __align__(128) unsigned char smem_raw[];
    __nv_bfloat16* Ws  = (__nv_bfloat16*)smem_raw;          // [32][WS_LD]
    __nv_bfloat16* Hs0 = Ws + 32 * WS_LD;                   // [32][HS_LD]
    __nv_bfloat16* Hs1 = Hs0 + 32 * HS_LD;
    __shared__ __align__(16) float Gs[2][32][GS_LD];        // K-split partial gates
    __shared__ float bsum[32];
    __shared__ uint64_t mbar[2];

    const int c0   = blockIdx.x * 8;    // first owned hidden column
    const int tid  = threadIdx.x;       // 256
    const int warp = tid >> 5;
    const int lane = tid & 31;
    const int wk = warp >> 2;           // K half
    const int wm = (warp >> 1) & 1;     // 16-row half of 32-row chunk
    const int wn = warp & 1;            // 16 of 32 gate cols

    // ---- W_hh slice -> bf16 smem (once). row n = gate(n>>3), col c0+(n&7) ----
    for (int i = tid; i < 32 * 256; i += 256) {
        int n = i >> 8, kv = i & 255;
        int g = n >> 3, col = n & 7;
        float4 v = *(const float4*)(Whh + (size_t)(g * HDIM + c0 + col) * HDIM + kv * 4);
        __nv_bfloat162 p0 = __floats2bfloat162_rn(v.x, v.y);
        __nv_bfloat162 p1 = __floats2bfloat162_rn(v.z, v.w);
        *(uint2*)(Ws + (size_t)n * WS_LD + kv * 4) = make_uint2(*(unsigned*)&p0, *(unsigned*)&p1);
    }
    if (tid < 32) {
        int g = tid >> 3, col = tid & 7;
        int r = g * HDIM + c0 + col;
        bsum[tid] = bih[r] + bhh[r];
    }
    if (tid == 0) { mbar_init(&mbar[0], 1); mbar_init(&mbar[1], 1); }
    __syncthreads();

    for (int s = 0; s < SEQ; s++) {
        const __nv_bfloat16* hin = g_hb[s & 1];
        __nv_bfloat16*       hob = g_hb[(s + 1) & 1];
        const __nv_bfloat16* xs  = g_xq + (size_t)s * 4096 * BATCH;

        if (warp == 0) {
            stage_chunk(Hs0, hin, 0, &mbar[0], lane);
            stage_chunk(Hs1, hin, 1, &mbar[1], lane);
        }

        for (int c = 0; c < 4; c++) {
            // each mbar completes exactly twice per step -> parity = (c>>1)&1
            mbar_wait(&mbar[c & 1], (unsigned)((c >> 1) & 1));
            const __nv_bfloat16* Hc = (c & 1) ? Hs1 : Hs0;

            wmma::fragment<wmma::accumulator, 16, 16, 16, float> acc;
            wmma::fill_fragment(acc, 0.0f);
            const int kb = wk * 512;
            #pragma unroll 8
            for (int ks = 0; ks < 32; ks++) {
                int k = kb + ks * 16;
                wmma::fragment<wmma::matrix_b, 16, 16, 16, __nv_bfloat16, wmma::col_major> bf;
                wmma::load_matrix_sync(bf, Ws + (size_t)(wn * 16) * WS_LD + k, WS_LD);
                wmma::fragment<wmma::matrix_a, 16, 16, 16, __nv_bfloat16, wmma::row_major> af;
                wmma::load_matrix_sync(af, Hc + (size_t)(wm * 16) * HS_LD + k, HS_LD);
                wmma::mma_sync(acc, af, bf, acc);
            }
            __syncthreads();            // all warps done reading this buffer

            if (c < 2 && warp == 0)     // refill consumed buffer with chunk c+2
                stage_chunk((c & 1) ? Hs1 : Hs0, hin, c + 2, &mbar[c & 1], lane);

            wmma::store_matrix_sync(&Gs[wk][wm * 16][wn * 16], acc, GS_LD, wmma::mem_row_major);
            __syncthreads();

            // ---- epilogue for this chunk's 32 batch rows (threads 0..127) ----
            if (tid < 128) {
                int bl = tid >> 2, cq = tid & 3;
                int bg = c * 32 + bl;
                float2 cprev = *(const float2*)&g_c[(size_t)bg * HDIM + c0 + cq * 2];
                float cc[2], hh[2];
                #pragma unroll
                for (int u = 0; u < 2; u++) {
                    int col = cq * 2 + u;
                    int hc  = c0 + col;
                    float gi = Gs[0][bl][col]      + Gs[1][bl][col]
                             + __bfloat162float(xs[(size_t)(       hc) * 128 + bg]) + bsum[col];
                    float gf = Gs[0][bl][ 8 + col] + Gs[1][bl][ 8 + col]
                             + __bfloat162float(xs[(size_t)(1024 + hc) * 128 + bg]) + bsum[ 8 + col];
                    float gg = Gs[0][bl][16 + col] + Gs[1][bl][16 + col]
                             + __bfloat162float(xs[(size_t)(2048 + hc) * 128 + bg]) + bsum[16 + col];
                    float go = Gs[0][bl][24 + col] + Gs[1][bl][24 + col]
                             + __bfloat162float(xs[(size_t)(3072 + hc) * 128 + bg]) + bsum[24 + col];

                    float iv = 1.f / (1.f + expf(-gi));
                    float fv = 1.f / (1.f + expf(-gf));
                    float ov = 1.f / (1.f + expf(-go));

                    float cp = (u == 0) ? cprev.x : cprev.y;
                    cc[u] = fv * cp + iv * tanhf(gg);
                    hh[u] = ov * tanhf(cc[u]);
                }
                *(float2*)&g_c[(size_t)bg * HDIM + c0 + cq * 2] = make_float2(cc[0], cc[1]);
                __nv_bfloat162 hp = __floats2bfloat162_rn(hh[0], hh[1]);
                *(unsigned*)&hob[(size_t)bg * HDIM + c0 + cq * 2] = *(unsigned*)&hp;
                if (s == SEQ - 1) {
                    g_hf[(size_t)(c0 + cq * 2)     * 128 + bg] = hh[0];
                    g_hf[(size_t)(c0 + cq * 2 + 1) * 128 + bg] = hh[1];
                }
            }
            // next chunk's post-GEMM __syncthreads orders Gs reuse
        }

        // ---- grid-wide step barrier ----
        if (s != SEQ - 1) {
            __syncthreads();
            if (tid == 0) {
                __threadfence();
                atomicAdd(&g_arrive, 1u);
                unsigned target = (unsigned)(s + 1) * (unsigned)GRID;
                while (atomicAdd(&g_arrive, 0u) < target) __nanosleep(32);
                __threadfence();
            }
            __syncthreads();
        }
    }
}

// ---------------------------------------------------------------------------
// Kernel 3: log_softmax over BATCH axis of final h (g_hf is [hc][b]).
// ---------------------------------------------------------------------------
__global__ void logsoftmax_kernel(float* __restrict__ out) {
    const int hj = blockIdx.x;
    const int t  = threadIdx.x;   // 128

    float v = g_hf[(size_t)hj * BATCH + t];

    __shared__ float rm[4], rs[4];
    float m = v;
    #pragma unroll
    for (int o = 16; o; o >>= 1) m = fmaxf(m, __shfl_xor_sync(0xffffffffu, m, o));
    if ((t & 31) == 0) rm[t >> 5] = m;
    __syncthreads();
    m = fmaxf(fmaxf(rm[0], rm[1]), fmaxf(rm[2], rm[3]));

    float e = expf(v - m);
    float ssum = e;
    #pragma unroll
    for (int o = 16; o; o >>= 1) ssum += __shfl_xor_sync(0xffffffffu, ssum, o);
    if ((t & 31) == 0) rs[t >> 5] = ssum;
    __syncthreads();
    ssum = rs[0] + rs[1] + rs[2] + rs[3];

    out[(size_t)t * HDIM + hj] = (v - m) - logf(ssum);
}

// ---------------------------------------------------------------------------
extern "C" void kernel_launch(void* const* d_in, const int* in_sizes, int n_in,
                              void* d_out, int out_size) {
    (void)in_sizes; (void)n_in; (void)out_size;
    const int*   X    = (const int*)d_in[0];
    const float* embd = (const float*)d_in[1];
    const float* Wih  = (const float*)d_in[2];
    const float* Whh  = (const float*)d_in[3];
    const float* bih  = (const float*)d_in[4];
    const float* bhh  = (const float*)d_in[5];
    float* out = (float*)d_out;

    static int configured = 0;
    if (!configured) {
        cudaFuncSetAttribute(lstm_persistent_kernel,
                             cudaFuncAttributeMaxDynamicSharedMemorySize, PERS_SMEM);
        cudaFuncSetAttribute(embed_proj_kernel,
                             cudaFuncAttributeMaxDynamicSharedMemorySize, EMB_SMEM);
        configured = 1;
    }

    zero_state_kernel<<<512, 256>>>();
    embed_proj_kernel<<<dim3(32, 512), 256, EMB_SMEM>>>(X, embd, Wih);
    lstm_persistent_kernel<<<GRID, 256, PERS_SMEM>>>(Whh, bih, bhh);
    logsoftmax_kernel<<<HDIM, BATCH>>>(out);
}

// round 10
// speedup vs baseline: 1.4372x; 1.0437x over previous
#include <cuda_runtime.h>
#include <cuda_bf16.h>
#include <mma.h>
#include <math.h>
#include <stdint.h>

using namespace nvcuda;

#define SEQ   512
#define BATCH 128
#define EDIM  1024
#define HDIM  1024
#define GRID  128
#define WS_LD 1032                     // 1024 K + 8 pad (elements)
#define HS_LD 1032
#define GS_LD 36                       // multiple of 4 floats (16B) for wmma
#define PERS_SMEM (3 * 32 * WS_LD * 2) // W + 2 h-chunk buffers = 198144 B
#define EMB_SMEM  (128 * 136 * 4)      // stage tile = 69632 B (overlays A/B bufs)

// ---- device scratch (no allocations allowed) ----
__device__ __align__(256) __nv_bfloat16 g_xq[(size_t)SEQ * 4096 * BATCH]; // [s][n][b] bf16
__device__ __align__(256) __nv_bfloat16 g_hb[2][BATCH * HDIM];            // [b][k] bf16, dbl-buffered
__device__ __align__(256) float g_hf[HDIM * BATCH];                       // final h, [hc][b]
__device__ __align__(256) float g_c[HDIM * BATCH];                        // cell state [hc][b]
__device__ unsigned g_arrive;

__device__ __forceinline__ unsigned sptr(const void* p) {
    return (unsigned)__cvta_generic_to_shared(p);
}
__device__ __forceinline__ void mbar_init(uint64_t* m, unsigned count) {
    asm volatile("mbarrier.init.shared.b64 [%0], %1;" :: "r"(sptr(m)), "r"(count));
}
__device__ __forceinline__ void mbar_expect(uint64_t* m, unsigned bytes) {
    asm volatile("mbarrier.arrive.expect_tx.shared.b64 _, [%0], %1;"
                 :: "r"(sptr(m)), "r"(bytes) : "memory");
}
__device__ __forceinline__ void bulk_g2s(void* dst, const void* src, unsigned bytes, uint64_t* m) {
    asm volatile("cp.async.bulk.shared::cta.global.mbarrier::complete_tx::bytes [%0], [%1], %2, [%3];"
                 :: "r"(sptr(dst)), "l"(src), "r"(bytes), "r"(sptr(m)) : "memory");
}
__device__ __forceinline__ void mbar_wait(uint64_t* m, unsigned parity) {
    asm volatile(
        "{\n\t.reg .pred P;\n\t"
        "W%=:\n\t"
        "mbarrier.try_wait.parity.acquire.cta.shared::cta.b64 P, [%0], %1;\n\t"
        "@P bra D%=;\n\t"
        "bra W%=;\n\t"
        "D%=:\n\t}"
        :: "r"(sptr(m)), "r"(parity) : "memory");
}

// ---------------------------------------------------------------------------
// Kernel 0: reset state (deterministic across graph replays)
// ---------------------------------------------------------------------------
__global__ void zero_state_kernel() {
    int i = blockIdx.x * blockDim.x + threadIdx.x;
    if (i < 16384) ((uint4*)g_hb[0])[i] = make_uint4(0u, 0u, 0u, 0u);
    if (i < 32768) ((float4*)g_c)[i]   = make_float4(0.f, 0.f, 0.f, 0.f);
    if (i == 0) g_arrive = 0u;
}

// ---------------------------------------------------------------------------
// Kernel 1: embedding gather + input projection (bf16 wmma, 128x128 tiles),
// output bf16 TRANSPOSED: g_xq[s][n][b]. Grid (32 n-tiles, 512 steps).
// ---------------------------------------------------------------------------
__global__ __launch_bounds__(256)
void embed_proj_kernel(const int* __restrict__ X,
                       const float* __restrict__ embd,
                       const float* __restrict__ Wih) {
    extern __shared__ __align__(16) unsigned char dyn[];
    __nv_bfloat16* As = (__nv_bfloat16*)dyn;        // [2][128][40]
    __nv_bfloat16* Bs = As + 2 * 128 * 40;          // [2][128][40]
    float* stage = (float*)dyn;                     // overlay after GEMM, col-major ld=136
    __shared__ int tok[128];

    const int s   = blockIdx.y;
    const int nt  = blockIdx.x;
    const int tid = threadIdx.x;
    const int warp = tid >> 5;
    const int wm = warp >> 2;         // 0..1 -> 64 m rows
    const int wn = warp & 3;          // 0..3 -> 32 n cols

    if (tid < 128) tok[tid] = X[s * 128 + tid];
    __syncthreads();

    wmma::fragment<wmma::accumulator, 16, 16, 16, float> acc[4][2];
    #pragma unroll
    for (int i = 0; i < 4; i++)
        #pragma unroll
        for (int j = 0; j < 2; j++) wmma::fill_fragment(acc[i][j], 0.0f);

    int rr[4], kk[4];
    #pragma unroll
    for (int q = 0; q < 4; q++) {
        int slot = q * 256 + tid;
        rr[q] = slot >> 3;
        kk[q] = slot & 7;
    }

    float4 ra[4], rb[4];
    auto ldg_chunk = [&](int kc) {
        #pragma unroll
        for (int q = 0; q < 4; q++) {
            ra[q] = *(const float4*)(embd + (size_t)tok[rr[q]] * EDIM + kc * 32 + kk[q] * 4);
            rb[q] = *(const float4*)(Wih + (size_t)(nt * 128 + rr[q]) * EDIM + kc * 32 + kk[q] * 4);
        }
    };
    auto sts_chunk = [&](int buf) {
        #pragma unroll
        for (int q = 0; q < 4; q++) {
            __nv_bfloat162 a0 = __floats2bfloat162_rn(ra[q].x, ra[q].y);
            __nv_bfloat162 a1 = __floats2bfloat162_rn(ra[q].z, ra[q].w);
            *(uint2*)(As + (size_t)(buf * 128 + rr[q]) * 40 + kk[q] * 4) =
                make_uint2(*(unsigned*)&a0, *(unsigned*)&a1);
            __nv_bfloat162 b0 = __floats2bfloat162_rn(rb[q].x, rb[q].y);
            __nv_bfloat162 b1 = __floats2bfloat162_rn(rb[q].z, rb[q].w);
            *(uint2*)(Bs + (size_t)(buf * 128 + rr[q]) * 40 + kk[q] * 4) =
                make_uint2(*(unsigned*)&b0, *(unsigned*)&b1);
        }
    };

    ldg_chunk(0);
    sts_chunk(0);
    __syncthreads();
    int buf = 0;

    for (int kc = 0; kc < 32; kc++) {
        if (kc < 31) ldg_chunk(kc + 1);
        #pragma unroll
        for (int ks = 0; ks < 2; ks++) {
            wmma::fragment<wmma::matrix_a, 16, 16, 16, __nv_bfloat16, wmma::row_major> af[4];
            wmma::fragment<wmma::matrix_b, 16, 16, 16, __nv_bfloat16, wmma::col_major> bf[2];
            #pragma unroll
            for (int i = 0; i < 4; i++)
                wmma::load_matrix_sync(af[i], As + (size_t)(buf * 128 + wm * 64 + i * 16) * 40 + ks * 16, 40);
            #pragma unroll
            for (int j = 0; j < 2; j++)
                wmma::load_matrix_sync(bf[j], Bs + (size_t)(buf * 128 + wn * 32 + j * 16) * 40 + ks * 16, 40);
            #pragma unroll
            for (int i = 0; i < 4; i++)
                #pragma unroll
                for (int j = 0; j < 2; j++)
                    wmma::mma_sync(acc[i][j], af[i], bf[j], acc[i][j]);
        }
        if (kc < 31) {
            sts_chunk(buf ^ 1);
            __syncthreads();
            buf ^= 1;
        }
    }

    __syncthreads();
    #pragma unroll
    for (int i = 0; i < 4; i++)
        #pragma unroll
        for (int j = 0; j < 2; j++)
            wmma::store_matrix_sync(stage + (wm * 64 + i * 16) + (size_t)(wn * 32 + j * 16) * 136,
                                    acc[i][j], 136, wmma::mem_col_major);
    __syncthreads();

    #pragma unroll
    for (int q = 0; q < 8; q++) {
        int slot = q * 256 + tid;
        int n   = slot >> 4;
        int seg = slot & 15;
        const float* src = stage + (size_t)n * 136 + seg * 8;
        __nv_bfloat162 p0 = __floats2bfloat162_rn(src[0], src[1]);
        __nv_bfloat162 p1 = __floats2bfloat162_rn(src[2], src[3]);
        __nv_bfloat162 p2 = __floats2bfloat162_rn(src[4], src[5]);
        __nv_bfloat162 p3 = __floats2bfloat162_rn(src[6], src[7]);
        uint4 u = make_uint4(*(unsigned*)&p0, *(unsigned*)&p1, *(unsigned*)&p2, *(unsigned*)&p3);
        *(uint4*)(g_xq + ((size_t)s * 4096 + nt * 128 + n) * 128 + seg * 8) = u;
    }
}

// ---------------------------------------------------------------------------
// Kernel 2: persistent LSTM. Per step: prefetch this block's x-gate values
// into registers (no h-dependency -> fully hidden), 4 batch-chunks of 32 rows
// staged via cp.async.bulk, dual-accumulator K-split GEMM, chunk-local
// epilogue with all 256 threads, light acquire-poll grid barrier.
// ---------------------------------------------------------------------------
__device__ __forceinline__ void stage_chunk(__nv_bfloat16* buf, const __nv_bfloat16* hin,
                                            int chunk, uint64_t* mb, int lane) {
    if (lane == 0) mbar_expect(mb, 32 * 2048);
    __syncwarp();
    bulk_g2s(buf + (size_t)lane * HS_LD,
             hin + (size_t)(chunk * 32 + lane) * HDIM, 2048, mb);
}

__global__ __launch_bounds__(256, 1)
void lstm_persistent_kernel(const float* __restrict__ Whh,
                            const float* __restrict__ bih,
                            const float* __restrict__ bhh) {
    extern __shared__ __align__(128) unsigned char smem_raw[];
    __nv_bfloat16* Ws  = (__nv_bfloat16*)smem_raw;          // [32][WS_LD]
    __nv_bfloat16* Hs0 = Ws + 32 * WS_LD;                   // [32][HS_LD]
    __nv_bfloat16* Hs1 = Hs0 + 32 * HS_LD;
    __shared__ __align__(16) float Gs[2][32][GS_LD];        // K-split partial gates
    __shared__ float bsum[32];
    __shared__ uint64_t mbar[2];

    const int c0   = blockIdx.x * 8;
    const int tid  = threadIdx.x;       // 256
    const int warp = tid >> 5;
    const int lane = tid & 31;
    const int wk = warp >> 2;           // K half
    const int wm = (warp >> 1) & 1;     // 16-row half of 32-row chunk
    const int wn = warp & 1;            // 16 of 32 gate cols

    // epilogue mapping: 1 cell/thread, warp-consecutive in batch
    const int ebl  = tid & 31;          // batch row within chunk
    const int ecol = tid >> 5;          // owned col 0..7
    const int ehc  = c0 + ecol;

    // ---- W_hh slice -> bf16 smem (once) ----
    for (int i = tid; i < 32 * 256; i += 256) {
        int n = i >> 8, kv = i & 255;
        int g = n >> 3, col = n & 7;
        float4 v = *(const float4*)(Whh + (size_t)(g * HDIM + c0 + col) * HDIM + kv * 4);
        __nv_bfloat162 p0 = __floats2bfloat162_rn(v.x, v.y);
        __nv_bfloat162 p1 = __floats2bfloat162_rn(v.z, v.w);
        *(uint2*)(Ws + (size_t)n * WS_LD + kv * 4) = make_uint2(*(unsigned*)&p0, *(unsigned*)&p1);
    }
    if (tid < 32) {
        int g = tid >> 3, col = tid & 7;
        int r = g * HDIM + c0 + col;
        bsum[tid] = bih[r] + bhh[r];
    }
    if (tid == 0) { mbar_init(&mbar[0], 1); mbar_init(&mbar[1], 1); }
    __syncthreads();

    for (int s = 0; s < SEQ; s++) {
        const __nv_bfloat16* hin = g_hb[s & 1];
        __nv_bfloat16*       hob = g_hb[(s + 1) & 1];
        const __nv_bfloat16* xs  = g_xq + (size_t)s * 4096 * BATCH;

        // ---- x-gate prefetch: 16 coalesced, independent DRAM loads/thread ----
        unsigned short xr[4][4];
        #pragma unroll
        for (int c = 0; c < 4; c++)
            #pragma unroll
            for (int g = 0; g < 4; g++)
                xr[c][g] = __ldcg((const unsigned short*)xs
                                  + (size_t)(g * 1024 + ehc) * 128 + c * 32 + ebl);

        if (warp == 0) {
            stage_chunk(Hs0, hin, 0, &mbar[0], lane);
            stage_chunk(Hs1, hin, 1, &mbar[1], lane);
        }

        for (int c = 0; c < 4; c++) {
            mbar_wait(&mbar[c & 1], (unsigned)((c >> 1) & 1));
            const __nv_bfloat16* Hc = (c & 1) ? Hs1 : Hs0;

            // dual-accumulator K-split: two interleaved 16-deep MMA chains
            wmma::fragment<wmma::accumulator, 16, 16, 16, float> acc0, acc1;
            wmma::fill_fragment(acc0, 0.0f);
            wmma::fill_fragment(acc1, 0.0f);
            const int kb = wk * 512;
            #pragma unroll
            for (int ks = 0; ks < 16; ks++) {
                int k0 = kb + ks * 32;
                wmma::fragment<wmma::matrix_b, 16, 16, 16, __nv_bfloat16, wmma::col_major> bf0, bf1;
                wmma::fragment<wmma::matrix_a, 16, 16, 16, __nv_bfloat16, wmma::row_major> af0, af1;
                wmma::load_matrix_sync(bf0, Ws + (size_t)(wn * 16) * WS_LD + k0, WS_LD);
                wmma::load_matrix_sync(af0, Hc + (size_t)(wm * 16) * HS_LD + k0, HS_LD);
                wmma::mma_sync(acc0, af0, bf0, acc0);
                wmma::load_matrix_sync(bf1, Ws + (size_t)(wn * 16) * WS_LD + k0 + 16, WS_LD);
                wmma::load_matrix_sync(af1, Hc + (size_t)(wm * 16) * HS_LD + k0 + 16, HS_LD);
                wmma::mma_sync(acc1, af1, bf1, acc1);
            }
            #pragma unroll
            for (int t = 0; t < acc0.num_elements; t++) acc0.x[t] += acc1.x[t];
            __syncthreads();            // all warps done reading this buffer

            if (c < 2 && warp == 0)     // refill consumed buffer with chunk c+2
                stage_chunk((c & 1) ? Hs1 : Hs0, hin, c + 2, &mbar[c & 1], lane);

            wmma::store_matrix_sync(&Gs[wk][wm * 16][wn * 16], acc0, GS_LD, wmma::mem_row_major);
            __syncthreads();

            // ---- epilogue: 1 cell/thread (32 rows x 8 cols = 256) ----
            {
                int bg = c * 32 + ebl;
                float gi = Gs[0][ebl][ecol]      + Gs[1][ebl][ecol]
                         + __bfloat162float(*(__nv_bfloat16*)&xr[c][0]) + bsum[ecol];
                float gf = Gs[0][ebl][ 8 + ecol] + Gs[1][ebl][ 8 + ecol]
                         + __bfloat162float(*(__nv_bfloat16*)&xr[c][1]) + bsum[ 8 + ecol];
                float gg = Gs[0][ebl][16 + ecol] + Gs[1][ebl][16 + ecol]
                         + __bfloat162float(*(__nv_bfloat16*)&xr[c][2]) + bsum[16 + ecol];
                float go = Gs[0][ebl][24 + ecol] + Gs[1][ebl][24 + ecol]
                         + __bfloat162float(*(__nv_bfloat16*)&xr[c][3]) + bsum[24 + ecol];

                float iv = 1.f / (1.f + expf(-gi));
                float fv = 1.f / (1.f + expf(-gf));
                float ov = 1.f / (1.f + expf(-go));

                int ci = ehc * BATCH + bg;                  // [hc][b]: coalesced
                float cn = fv * g_c[ci] + iv * tanhf(gg);
                float hn = ov * tanhf(cn);
                g_c[ci] = cn;
                hob[(size_t)bg * HDIM + ehc] = __float2bfloat16(hn);
                if (s == SEQ - 1) g_hf[ci] = hn;
            }
            // next chunk's post-GEMM __syncthreads orders Gs reuse
        }

        // ---- grid-wide step barrier (acquire-poll, no atomic RMW spin) ----
        if (s != SEQ - 1) {
            __syncthreads();
            if (tid == 0) {
                __threadfence();
                atomicAdd(&g_arrive, 1u);
                unsigned target = (unsigned)(s + 1) * (unsigned)GRID;
                unsigned v;
                do {
                    asm volatile("ld.acquire.gpu.global.u32 %0, [%1];"
                                 : "=r"(v) : "l"(&g_arrive));
                    if (v >= target) break;
                    __nanosleep(32);
                } while (true);
            }
            __syncthreads();
        }
    }
}

// ---------------------------------------------------------------------------
// Kernel 3: log_softmax over BATCH axis of final h (g_hf is [hc][b]).
// ---------------------------------------------------------------------------
__global__ void logsoftmax_kernel(float* __restrict__ out) {
    const int hj = blockIdx.x;
    const int t  = threadIdx.x;   // 128

    float v = g_hf[(size_t)hj * BATCH + t];

    __shared__ float rm[4], rs[4];
    float m = v;
    #pragma unroll
    for (int o = 16; o; o >>= 1) m = fmaxf(m, __shfl_xor_sync(0xffffffffu, m, o));
    if ((t & 31) == 0) rm[t >> 5] = m;
    __syncthreads();
    m = fmaxf(fmaxf(rm[0], rm[1]), fmaxf(rm[2], rm[3]));

    float e = expf(v - m);
    float ssum = e;
    #pragma unroll
    for (int o = 16; o; o >>= 1) ssum += __shfl_xor_sync(0xffffffffu, ssum, o);
    if ((t & 31) == 0) rs[t >> 5] = ssum;
    __syncthreads();
    ssum = rs[0] + rs[1] + rs[2] + rs[3];

    out[(size_t)t * HDIM + hj] = (v - m) - logf(ssum);
}

// ---------------------------------------------------------------------------
extern "C" void kernel_launch(void* const* d_in, const int* in_sizes, int n_in,
                              void* d_out, int out_size) {
    (void)in_sizes; (void)n_in; (void)out_size;
    const int*   X    = (const int*)d_in[0];
    const float* embd = (const float*)d_in[1];
    const float* Wih  = (const float*)d_in[2];
    const float* Whh  = (const float*)d_in[3];
    const float* bih  = (const float*)d_in[4];
    const float* bhh  = (const float*)d_in[5];
    float* out = (float*)d_out;

    static int configured = 0;
    if (!configured) {
        cudaFuncSetAttribute(lstm_persistent_kernel,
                             cudaFuncAttributeMaxDynamicSharedMemorySize, PERS_SMEM);
        cudaFuncSetAttribute(embed_proj_kernel,
                             cudaFuncAttributeMaxDynamicSharedMemorySize, EMB_SMEM);
        configured = 1;
    }

    zero_state_kernel<<<512, 256>>>();
    embed_proj_kernel<<<dim3(32, 512), 256, EMB_SMEM>>>(X, embd, Wih);
    lstm_persistent_kernel<<<GRID, 256, PERS_SMEM>>>(Whh, bih, bhh);
    logsoftmax_kernel<<<HDIM, BATCH>>>(out);
}